// round 1
// baseline (speedup 1.0000x reference)
#include <cuda_runtime.h>

// ExRestSelfAtten: fused windowed self-attention block.
// One CTA per batch element (B=1024), 512 threads, all intermediates in SMEM.
//
// Key identity: x_nei @ Wk are just shifted rows of (h @ Wk), so K and V are
// computed ONCE per sequence (100x128 each) and the 5-neighbor window is a
// shifted gather. Out-of-bounds neighbors: key row = 0 => score = 0 (still in
// softmax), value row = bv.

#define B_    1024
#define S_    100
#define IN_   100
#define H_    128
#define MID_  32
#define OUT_  2
#define NTHREADS 512

// SMEM layout (floats):
//  sh   [     0 .. 12800)  h (100x128)
//  sq   [ 12800 .. 25600)  q (also overlaid by x[100x100]=10000 during phase 1)
//  sk   [ 25600 .. 38400)  k
//  sv   [ 38400 .. 51200)  v
//  wb   [ 51200 .. 55296)  weight staging (4096 floats = 16KB; holds W2 in phase 3)
//  sctx [ 55296 .. 57344)  per-warp context scratch (16 warps x 128)
//  sbv  [ 57344 .. 57472)  bv
//  sb2  [ 57472 .. 57504)  b2
//  sW3  [ 57504 .. 57568)  W3 (32x2)
//  sb3  [ 57568 .. 57570)  b3
#define SMEM_FLOATS 57570
#define SMEM_BYTES  (SMEM_FLOATS * 4)

__global__ __launch_bounds__(NTHREADS, 1)
void exrest_fused_kernel(const float* __restrict__ x,  const float* __restrict__ W1,
                         const float* __restrict__ b1, const float* __restrict__ Wq,
                         const float* __restrict__ Wk, const float* __restrict__ Wv,
                         const float* __restrict__ bv, const float* __restrict__ W2,
                         const float* __restrict__ b2, const float* __restrict__ W3,
                         const float* __restrict__ b3, const float* __restrict__ pe,
                         float* __restrict__ out, float* __restrict__ wout)
{
    extern __shared__ float sm[];
    float* sh   = sm;
    float* sq   = sm + 12800;
    float* sk   = sm + 25600;
    float* sv   = sm + 38400;
    float* wb   = sm + 51200;
    float* sctx = sm + 55296;
    float* sbv  = sm + 57344;
    float* sb2  = sm + 57472;
    float* sW3  = sm + 57504;
    float* sb3  = sm + 57568;

    const int tid  = threadIdx.x;
    const int lane = tid & 31;
    const int ty   = tid >> 5;     // warp id, 0..15
    const int bb   = blockIdx.x;

    // ---- Phase 0: stage x[bb] (into the q region) + small constants ----
    {
        const float* xb = x + (long long)bb * (S_ * IN_);
        for (int i = tid; i < S_ * IN_; i += NTHREADS) sq[i] = xb[i];
        if (tid < H_)   sbv[tid] = bv[tid];
        if (tid < MID_) sb2[tid] = b2[tid];
        if (tid < MID_ * OUT_) sW3[tid] = W3[tid];
        if (tid < OUT_) sb3[tid] = b3[tid];
    }
    __syncthreads();

    // ---- Phase 1: h = relu(x @ W1 + b1) + pe  (100x100 @ 100x128) ----
    {
        float acc[7][4];
        #pragma unroll
        for (int i = 0; i < 7; i++)
            #pragma unroll
            for (int j = 0; j < 4; j++) acc[i][j] = 0.f;

        const float* xrow[7];
        #pragma unroll
        for (int i = 0; i < 7; i++) {
            int r = ty + 16 * i;
            xrow[i] = sq + (r < S_ ? r : 0) * IN_;   // clamped (store-guarded later)
        }

        for (int k0 = 0; k0 < IN_; k0 += 25) {
            for (int i = tid; i < 25 * H_; i += NTHREADS) wb[i] = W1[k0 * H_ + i];
            __syncthreads();
            #pragma unroll
            for (int kk = 0; kk < 25; kk++) {
                float wv4[4];
                #pragma unroll
                for (int j = 0; j < 4; j++) wv4[j] = wb[kk * H_ + lane + 32 * j];
                #pragma unroll
                for (int i = 0; i < 7; i++) {
                    float xv = xrow[i][k0 + kk];
                    #pragma unroll
                    for (int j = 0; j < 4; j++) acc[i][j] = fmaf(xv, wv4[j], acc[i][j]);
                }
            }
            __syncthreads();
        }

        #pragma unroll
        for (int i = 0; i < 7; i++) {
            int r = ty + 16 * i;
            if (r < S_) {
                #pragma unroll
                for (int j = 0; j < 4; j++) {
                    int c = lane + 32 * j;
                    float v = acc[i][j] + b1[c];
                    v = fmaxf(v, 0.f) + pe[r * H_ + c];
                    sh[r * H_ + c] = v;
                }
            }
        }
    }
    __syncthreads();   // h ready; x region (sq) now free

    // ---- Phase 2: q = h@Wq, k = h@Wk, v = h@Wv + bv  (100x128 @ 128x128) ----
    {
        const float* hrow[7];
        #pragma unroll
        for (int i = 0; i < 7; i++) {
            int r = ty + 16 * i;
            hrow[i] = sh + (r < S_ ? r : 0) * H_;
        }

        const float* Wsel[3] = { Wq, Wk, Wv };
        float*       dsel[3] = { sq, sk, sv };

        for (int ws = 0; ws < 3; ws++) {
            const float* W = Wsel[ws];
            float* dst = dsel[ws];

            float acc[7][4];
            #pragma unroll
            for (int i = 0; i < 7; i++)
                #pragma unroll
                for (int j = 0; j < 4; j++) acc[i][j] = 0.f;

            for (int k0 = 0; k0 < H_; k0 += 32) {
                for (int i = tid; i < 32 * H_; i += NTHREADS) wb[i] = W[k0 * H_ + i];
                __syncthreads();
                #pragma unroll
                for (int kk = 0; kk < 32; kk++) {
                    float wv4[4];
                    #pragma unroll
                    for (int j = 0; j < 4; j++) wv4[j] = wb[kk * H_ + lane + 32 * j];
                    #pragma unroll
                    for (int i = 0; i < 7; i++) {
                        float hv = hrow[i][k0 + kk];
                        #pragma unroll
                        for (int j = 0; j < 4; j++) acc[i][j] = fmaf(hv, wv4[j], acc[i][j]);
                    }
                }
                __syncthreads();
            }

            #pragma unroll
            for (int i = 0; i < 7; i++) {
                int r = ty + 16 * i;
                if (r < S_) {
                    #pragma unroll
                    for (int j = 0; j < 4; j++) {
                        int c = lane + 32 * j;
                        float v = acc[i][j];
                        if (ws == 2) v += sbv[c];
                        dst[r * H_ + c] = v;
                    }
                }
            }
            __syncthreads();
        }
    }

    // ---- Phase 3: attention window + softmax + context + FFN ----
    for (int i = tid; i < H_ * MID_; i += NTHREADS) wb[i] = W2[i];  // stage W2
    __syncthreads();

    const float INV_SQRT_H = 0.08838834764831845f;  // 1/sqrt(128)

    for (int s = ty; s < S_; s += 16) {
        // scores over 5 neighbors: neighbor index j = s + 2 - m
        float sc[5];
        #pragma unroll
        for (int m = 0; m < 5; m++) {
            int j = s + 2 - m;
            float p = 0.f;
            if (j >= 0 && j < S_) {
                #pragma unroll
                for (int i = 0; i < 4; i++)
                    p = fmaf(sq[s * H_ + lane + 32 * i], sk[j * H_ + lane + 32 * i], p);
            }
            #pragma unroll
            for (int off = 16; off > 0; off >>= 1)
                p += __shfl_xor_sync(0xffffffffu, p, off);
            sc[m] = p * INV_SQRT_H;   // OOB -> exactly 0, still in softmax
        }

        float mx = sc[0];
        #pragma unroll
        for (int m = 1; m < 5; m++) mx = fmaxf(mx, sc[m]);
        float e[5], sum = 0.f;
        #pragma unroll
        for (int m = 0; m < 5; m++) { e[m] = __expf(sc[m] - mx); sum += e[m]; }
        float rs = 1.f / sum;

        if (lane == 0) {
            float* wp = wout + ((long long)bb * S_ + s) * 5;
            #pragma unroll
            for (int m = 0; m < 5; m++) wp[m] = e[m] * rs;
        }

        // context = sum_m w_m * V[j]  (OOB -> bv)
        float ctx[4];
        #pragma unroll
        for (int i = 0; i < 4; i++) ctx[i] = 0.f;
        #pragma unroll
        for (int m = 0; m < 5; m++) {
            int j = s + 2 - m;
            float wm = e[m] * rs;
            const float* vp = (j >= 0 && j < S_) ? (sv + j * H_) : sbv;
            #pragma unroll
            for (int i = 0; i < 4; i++)
                ctx[i] = fmaf(wm, vp[lane + 32 * i], ctx[i]);
        }
        #pragma unroll
        for (int i = 0; i < 4; i++) sctx[ty * H_ + lane + 32 * i] = ctx[i];
        __syncwarp();

        // mid = relu(ctx @ W2 + b2): one output channel per lane (MID_=32)
        float mid = sb2[lane];
        #pragma unroll 8
        for (int k = 0; k < H_; k++)
            mid = fmaf(sctx[ty * H_ + k], wb[k * MID_ + lane], mid);
        mid = fmaxf(mid, 0.f);

        // out = mid @ W3 + b3 (OUT_=2), warp-reduce
        float p0 = mid * sW3[lane * 2 + 0];
        float p1 = mid * sW3[lane * 2 + 1];
        #pragma unroll
        for (int off = 16; off > 0; off >>= 1) {
            p0 += __shfl_xor_sync(0xffffffffu, p0, off);
            p1 += __shfl_xor_sync(0xffffffffu, p1, off);
        }
        if (lane == 0) {
            float* op = out + ((long long)bb * S_ + s) * 2;
            op[0] = p0 + sb3[0];
            op[1] = p1 + sb3[1];
        }
        __syncwarp();   // sctx reused next token by this warp
    }
}

extern "C" void kernel_launch(void* const* d_in, const int* in_sizes, int n_in,
                              void* d_out, int out_size)
{
    const float* x  = (const float*)d_in[0];
    const float* W1 = (const float*)d_in[1];
    const float* b1 = (const float*)d_in[2];
    const float* Wq = (const float*)d_in[3];
    const float* Wk = (const float*)d_in[4];
    const float* Wv = (const float*)d_in[5];
    const float* bv = (const float*)d_in[6];
    const float* W2 = (const float*)d_in[7];
    const float* b2 = (const float*)d_in[8];
    const float* W3 = (const float*)d_in[9];
    const float* b3 = (const float*)d_in[10];
    const float* pe = (const float*)d_in[11];

    float* out  = (float*)d_out;                    // (B,S,2) = 204800 floats
    float* wout = out + (long long)B_ * S_ * OUT_;  // (B,S,1,5) = 512000 floats

    cudaFuncSetAttribute(exrest_fused_kernel,
                         cudaFuncAttributeMaxDynamicSharedMemorySize, SMEM_BYTES);

    exrest_fused_kernel<<<B_, NTHREADS, SMEM_BYTES>>>(
        x, W1, b1, Wq, Wk, Wv, bv, W2, b2, W3, b3, pe, out, wout);
}

// round 2
// speedup vs baseline: 2.1713x; 2.1713x over previous
#include <cuda_runtime.h>

// ExRestSelfAtten fused kernel, round 2: packed f32x2 FFMA (fma.rn.f32x2)
// with K-paired operands. One CTA per batch (B=1024), 512 threads.

#define B_    1024
#define S_    100
#define IN_   100
#define H_    128
#define MID_  32
#define OUT_  2
#define NTHREADS 512

// SMEM layout (floats):
//  sh   [     0 .. 12800)  h (100x128); phase3: ctx scratch (16 warps x 2 x 128)
//  sq   [ 12800 .. 25600)  x staging (100x100) then q
//  sk   [ 25600 .. 38400)  k
//  sv   [ 38400 .. 51200)  v
//  wb   [ 51200 .. 55296)  weight staging, K-paired float2 (<=2048 pairs)
//  sbv  [ 55296 .. 55424)  bv
//  sb2  [ 55424 .. 55456)  b2
//  sW3  [ 55456 .. 55520)  W3
//  sb3  [ 55520 .. 55522)  b3
#define SMEM_FLOATS 55522
#define SMEM_BYTES  (SMEM_FLOATS * 4)

typedef unsigned long long u64;

// packed f32x2 fma: d = a*b + d (elementwise on the two fp32 lanes)
__device__ __forceinline__ void fma2(u64& d, u64 a, u64 b) {
    asm volatile("fma.rn.f32x2 %0, %1, %2, %0;" : "+l"(d) : "l"(a), "l"(b));
}
__device__ __forceinline__ u64 pk(float lo, float hi) {
    u64 r; asm("mov.b64 %0, {%1, %2};" : "=l"(r) : "f"(lo), "f"(hi)); return r;
}
__device__ __forceinline__ float2 up(u64 v) {
    float2 r; asm("mov.b64 {%0, %1}, %2;" : "=f"(r.x), "=f"(r.y) : "l"(v)); return r;
}

__global__ __launch_bounds__(NTHREADS, 1)
void exrest_fused_kernel(const float* __restrict__ x,  const float* __restrict__ W1,
                         const float* __restrict__ b1, const float* __restrict__ Wq,
                         const float* __restrict__ Wk, const float* __restrict__ Wv,
                         const float* __restrict__ bv, const float* __restrict__ W2,
                         const float* __restrict__ b2, const float* __restrict__ W3,
                         const float* __restrict__ b3, const float* __restrict__ pe,
                         float* __restrict__ out, float* __restrict__ wout)
{
    extern __shared__ float sm[];
    float* sh   = sm;            // also sctx in phase 3
    float* sq   = sm + 12800;
    float* sk   = sm + 25600;
    float* sv   = sm + 38400;
    float* wb   = sm + 51200;
    float* sbv  = sm + 55296;
    float* sb2  = sm + 55424;
    float* sW3  = sm + 55456;
    float* sb3  = sm + 55520;

    float2* wbf2 = (float2*)wb;
    const u64* wbu = (const u64*)wb;

    const int tid  = threadIdx.x;
    const int lane = tid & 31;
    const int ty   = tid >> 5;     // warp id, 0..15
    const int bb   = blockIdx.x;

    // ---- Phase 0: stage x[bb] (float4) + small constants ----
    {
        const float4* xb4 = (const float4*)(x + (long long)bb * (S_ * IN_));
        float4* sq4 = (float4*)sq;
        for (int i = tid; i < (S_ * IN_) / 4; i += NTHREADS) sq4[i] = xb4[i];
        if (tid < H_)   sbv[tid] = bv[tid];
        if (tid < MID_) sb2[tid] = b2[tid];
        if (tid < MID_ * OUT_) sW3[tid] = W3[tid];
        if (tid < OUT_) sb3[tid] = b3[tid];
    }
    __syncthreads();

    // ---- Phase 1: h = relu(x @ W1 + b1) + pe  (100x100 @ 100x128) ----
    {
        u64 acc[7][4];
        #pragma unroll
        for (int i = 0; i < 7; i++)
            #pragma unroll
            for (int j = 0; j < 4; j++) acc[i][j] = 0ull;

        const u64* xu[7];
        #pragma unroll
        for (int i = 0; i < 7; i++) {
            int r = ty + 16 * i;
            xu[i] = (const u64*)(sq + (r < S_ ? r : 0) * IN_);
        }

        // 5 chunks of 20 k (10 k-pairs)
        for (int c = 0; c < 5; c++) {
            const int k0 = 20 * c;
            __syncthreads();                 // wb free
            for (int e = tid; e < 10 * H_; e += NTHREADS) {
                int kp = e >> 7, col = e & 127;
                float2 g;
                g.x = W1[(k0 + 2 * kp    ) * H_ + col];
                g.y = W1[(k0 + 2 * kp + 1) * H_ + col];
                wbf2[e] = g;
            }
            __syncthreads();                 // wb ready
            const int k0h = 10 * c;
            #pragma unroll
            for (int kp = 0; kp < 10; kp += 2) {
                u64 w0[4], w1[4];
                #pragma unroll
                for (int j = 0; j < 4; j++) {
                    w0[j] = wbu[ kp      * H_ + lane + 32 * j];
                    w1[j] = wbu[(kp + 1) * H_ + lane + 32 * j];
                }
                #pragma unroll
                for (int i = 0; i < 7; i++) {
                    u64 a0 = xu[i][k0h + kp];
                    u64 a1 = xu[i][k0h + kp + 1];
                    #pragma unroll
                    for (int j = 0; j < 4; j++) {
                        fma2(acc[i][j], a0, w0[j]);
                        fma2(acc[i][j], a1, w1[j]);
                    }
                }
            }
        }

        #pragma unroll
        for (int i = 0; i < 7; i++) {
            int r = ty + 16 * i;
            if (r < S_) {
                #pragma unroll
                for (int j = 0; j < 4; j++) {
                    int c = lane + 32 * j;
                    float2 a = up(acc[i][j]);
                    float v = a.x + a.y + b1[c];
                    v = fmaxf(v, 0.f) + pe[r * H_ + c];
                    sh[r * H_ + c] = v;
                }
            }
        }
    }
    // (sync provided at top of phase-2 chunk loop)

    // ---- Phase 2: q = h@Wq, k = h@Wk, v = h@Wv + bv  (12 chunks of 32 k) ----
    {
        const u64* hu[7];
        int rr[7];
        #pragma unroll
        for (int i = 0; i < 7; i++) {
            int r = ty + 16 * i;
            rr[i] = r;
            hu[i] = (const u64*)(sh + (r < S_ ? r : 0) * H_);
        }

        const float* Wsel[3] = { Wq, Wk, Wv };
        float*       dsel[3] = { sq, sk, sv };

        u64 acc[7][4];
        #pragma unroll
        for (int i = 0; i < 7; i++)
            #pragma unroll
            for (int j = 0; j < 4; j++) acc[i][j] = 0ull;

        // prefetch registers for the next chunk (4 pair-elements / thread)
        float2 g[4];
        {
            const float* W = Wsel[0];
            #pragma unroll
            for (int t = 0; t < 4; t++) {
                int e = tid + NTHREADS * t;
                int kp = e >> 7, col = e & 127;
                g[t].x = W[(2 * kp    ) * H_ + col];
                g[t].y = W[(2 * kp + 1) * H_ + col];
            }
        }

        for (int cc = 0; cc < 12; cc++) {
            const int ws  = cc >> 2;
            const int k0h = (cc & 3) * 16;

            __syncthreads();                 // wb free (prev compute done)
            #pragma unroll
            for (int t = 0; t < 4; t++) wbf2[tid + NTHREADS * t] = g[t];
            __syncthreads();                 // wb ready

            if (cc < 11) {
                const int nc  = cc + 1;
                const float* W = Wsel[nc >> 2];
                const int nk0 = (nc & 3) * 32;
                #pragma unroll
                for (int t = 0; t < 4; t++) {
                    int e = tid + NTHREADS * t;
                    int kp = e >> 7, col = e & 127;
                    g[t].x = W[(nk0 + 2 * kp    ) * H_ + col];
                    g[t].y = W[(nk0 + 2 * kp + 1) * H_ + col];
                }
            }

            #pragma unroll
            for (int kp = 0; kp < 16; kp += 2) {
                u64 w0[4], w1[4];
                #pragma unroll
                for (int j = 0; j < 4; j++) {
                    w0[j] = wbu[ kp      * H_ + lane + 32 * j];
                    w1[j] = wbu[(kp + 1) * H_ + lane + 32 * j];
                }
                #pragma unroll
                for (int i = 0; i < 7; i++) {
                    u64 a0 = hu[i][k0h + kp];
                    u64 a1 = hu[i][k0h + kp + 1];
                    #pragma unroll
                    for (int j = 0; j < 4; j++) {
                        fma2(acc[i][j], a0, w0[j]);
                        fma2(acc[i][j], a1, w1[j]);
                    }
                }
            }

            if ((cc & 3) == 3) {             // end of one GEMM: write out
                float* dst = dsel[ws];
                #pragma unroll
                for (int i = 0; i < 7; i++) {
                    if (rr[i] < S_) {
                        #pragma unroll
                        for (int j = 0; j < 4; j++) {
                            int c = lane + 32 * j;
                            float2 a = up(acc[i][j]);
                            float v = a.x + a.y;
                            if (ws == 2) v += sbv[c];
                            dst[rr[i] * H_ + c] = v;
                        }
                    }
                }
                #pragma unroll
                for (int i = 0; i < 7; i++)
                    #pragma unroll
                    for (int j = 0; j < 4; j++) acc[i][j] = 0ull;
            }
        }
    }
    __syncthreads();   // q/k/v ready; sh free for ctx scratch; wb free

    // ---- Phase 3: attention + softmax + context + FFN (2 tokens / warp) ----
    // stage W2 K-paired: wbf2[kp*32+col] = (W2[2kp][col], W2[2kp+1][col])
    for (int e = tid; e < 64 * MID_; e += NTHREADS) {
        int kp = e >> 5, col = e & 31;
        float2 g;
        g.x = W2[(2 * kp    ) * MID_ + col];
        g.y = W2[(2 * kp + 1) * MID_ + col];
        wbf2[e] = g;
    }
    __syncthreads();

    const float INV_SQRT_H = 0.08838834764831845f;  // 1/sqrt(128)
    float* sctx = sh;
    const float w3a = sW3[lane * 2 + 0];
    const float w3b = sW3[lane * 2 + 1];
    const float b2l = sb2[lane];
    const float b30 = sb3[0], b31 = sb3[1];

    for (int sb = ty * 2; sb < S_; sb += 32) {
        #pragma unroll
        for (int t = 0; t < 2; t++) {
            int s = sb + t;
            if (s >= S_) break;

            const u64* qu = (const u64*)(sq + s * H_ + lane * 4);
            u64 qa = qu[0], qb = qu[1];

            float sc[5];
            #pragma unroll
            for (int m = 0; m < 5; m++) {
                int j = s + 2 - m;
                float pf = 0.f;
                if (j >= 0 && j < S_) {
                    const u64* ku = (const u64*)(sk + j * H_ + lane * 4);
                    u64 p = 0ull;
                    fma2(p, qa, ku[0]);
                    fma2(p, qb, ku[1]);
                    float2 pp = up(p);
                    pf = pp.x + pp.y;
                }
                #pragma unroll
                for (int off = 16; off > 0; off >>= 1)
                    pf += __shfl_xor_sync(0xffffffffu, pf, off);
                sc[m] = pf * INV_SQRT_H;
            }

            float mx = sc[0];
            #pragma unroll
            for (int m = 1; m < 5; m++) mx = fmaxf(mx, sc[m]);
            float e5[5], sum = 0.f;
            #pragma unroll
            for (int m = 0; m < 5; m++) { e5[m] = __expf(sc[m] - mx); sum += e5[m]; }
            float rs = 1.f / sum;

            if (lane == 0) {
                float* wp = wout + ((long long)bb * S_ + s) * 5;
                #pragma unroll
                for (int m = 0; m < 5; m++) wp[m] = e5[m] * rs;
            }

            u64 c0 = 0ull, c1 = 0ull;
            #pragma unroll
            for (int m = 0; m < 5; m++) {
                int j = s + 2 - m;
                float wm = e5[m] * rs;
                u64 wmp = pk(wm, wm);
                const float* vb = (j >= 0 && j < S_) ? (sv + j * H_) : sbv;
                const u64* vu = (const u64*)(vb + lane * 4);
                fma2(c0, wmp, vu[0]);
                fma2(c1, wmp, vu[1]);
            }
            u64* cd = (u64*)(sctx + (ty * 2 + t) * H_ + lane * 4);
            cd[0] = c0;
            cd[1] = c1;
        }
        __syncwarp();

        // mid = relu(ctx @ W2 + b2), both tokens share the W2-pair loads
        const u64* c0u = (const u64*)(sctx + (ty * 2) * H_);
        const u64* c1u = c0u + 64;
        u64 m0 = 0ull, m1 = 0ull;
        #pragma unroll
        for (int kp = 0; kp < 64; kp += 2) {
            u64 w0 = wbu[ kp      * MID_ + lane];
            u64 w1 = wbu[(kp + 1) * MID_ + lane];
            fma2(m0, c0u[kp],     w0);
            fma2(m0, c0u[kp + 1], w1);
            fma2(m1, c1u[kp],     w0);
            fma2(m1, c1u[kp + 1], w1);
        }

        #pragma unroll
        for (int t = 0; t < 2; t++) {
            int s = sb + t;
            if (s >= S_) break;
            float2 mm = up(t ? m1 : m0);
            float mid = fmaxf(mm.x + mm.y + b2l, 0.f);
            float p0 = mid * w3a;
            float p1 = mid * w3b;
            #pragma unroll
            for (int off = 16; off > 0; off >>= 1) {
                p0 += __shfl_xor_sync(0xffffffffu, p0, off);
                p1 += __shfl_xor_sync(0xffffffffu, p1, off);
            }
            if (lane == 0) {
                float* op = out + ((long long)bb * S_ + s) * 2;
                op[0] = p0 + b30;
                op[1] = p1 + b31;
            }
        }
        __syncwarp();
    }
}

extern "C" void kernel_launch(void* const* d_in, const int* in_sizes, int n_in,
                              void* d_out, int out_size)
{
    const float* x  = (const float*)d_in[0];
    const float* W1 = (const float*)d_in[1];
    const float* b1 = (const float*)d_in[2];
    const float* Wq = (const float*)d_in[3];
    const float* Wk = (const float*)d_in[4];
    const float* Wv = (const float*)d_in[5];
    const float* bv = (const float*)d_in[6];
    const float* W2 = (const float*)d_in[7];
    const float* b2 = (const float*)d_in[8];
    const float* W3 = (const float*)d_in[9];
    const float* b3 = (const float*)d_in[10];
    const float* pe = (const float*)d_in[11];

    float* out  = (float*)d_out;                    // (B,S,2)
    float* wout = out + (long long)B_ * S_ * OUT_;  // (B,S,1,5)

    cudaFuncSetAttribute(exrest_fused_kernel,
                         cudaFuncAttributeMaxDynamicSharedMemorySize, SMEM_BYTES);

    exrest_fused_kernel<<<B_, NTHREADS, SMEM_BYTES>>>(
        x, W1, b1, Wq, Wk, Wv, bv, W2, b2, W3, b3, pe, out, wout);
}